// round 12
// baseline (speedup 1.0000x reference)
#include <cuda_runtime.h>
#include <cuda_fp16.h>

#define N_NODES 100000
#define N_EDGES 1600000
#define F_IN 512
#define HIDDEN 16
#define N_CLASSES 40
#define BUCKET 128                     // CSR slots per node (P(deg>128) ~ 1e-60)

// ---------------- scratch (no device allocs; zero at module load) ------------
__device__ int   g_csr [N_NODES * BUCKET];   // bucket CSR: sources of in-edges
__device__ int   g_cnt [N_NODES];            // in-degree/cursor (self-cleaned by k_gather2)
__device__ uint2 g_hs1u[N_NODES * 4];        // x@W1 as fp16 (unscaled, gemm1 out)
__device__ uint2 g_hs1h[N_NODES * 4];        // (x@W1)*dis as fp16
__device__ uint2 g_hs2h[N_NODES * 4];        // relu(...)*dis as fp16

// ---------------- helpers ----------------
__device__ __forceinline__ unsigned long long pack2(float x, float y) {
    unsigned long long r;
    asm("mov.b64 %0, {%1,%2};" : "=l"(r) : "f"(x), "f"(y));
    return r;
}
__device__ __forceinline__ float2 unpack2(unsigned long long v) {
    float2 f;
    asm("mov.b64 {%0,%1}, %2;" : "=f"(f.x), "=f"(f.y) : "l"(v));
    return f;
}
__device__ __forceinline__ void ffma2(unsigned long long& d,
                                      unsigned long long a,
                                      unsigned long long b) {
    asm("fma.rn.f32x2 %0, %1, %2, %0;" : "+l"(d) : "l"(a), "l"(b));
}
__device__ __forceinline__ unsigned smem_u32(const void* p) {
    return (unsigned)__cvta_generic_to_shared(p);
}
__device__ __forceinline__ float4 h4_to_f4(uint2 u) {
    __half2 a = *reinterpret_cast<__half2*>(&u.x);
    __half2 b = *reinterpret_cast<__half2*>(&u.y);
    float2 fa = __half22float2(a), fb = __half22float2(b);
    return make_float4(fa.x, fa.y, fb.x, fb.y);
}
__device__ __forceinline__ uint2 f4_to_h4(float4 v) {
    __half2 a = __floats2half2_rn(v.x, v.y);
    __half2 b = __floats2half2_rn(v.z, v.w);
    uint2 u;
    u.x = *reinterpret_cast<unsigned*>(&a);
    u.y = *reinterpret_cast<unsigned*>(&b);
    return u;
}
// fp16 pairwise add of two packed-4-half values
__device__ __forceinline__ uint2 h4add(uint2 a, uint2 b) {
    __half2 ax = *reinterpret_cast<__half2*>(&a.x);
    __half2 ay = *reinterpret_cast<__half2*>(&a.y);
    __half2 bx = *reinterpret_cast<__half2*>(&b.x);
    __half2 by = *reinterpret_cast<__half2*>(&b.y);
    __half2 cx = __hadd2(ax, bx);
    __half2 cy = __hadd2(ay, by);
    uint2 c;
    c.x = *reinterpret_cast<unsigned*>(&cx);
    c.y = *reinterpret_cast<unsigned*>(&cy);
    return c;
}
__device__ __forceinline__ void f4acc(float4& a, float4 b) {
    a.x += b.x; a.y += b.y; a.z += b.z; a.w += b.w;
}

// Per-warp dtype detect: int64 (<2^31) => hi 32-bit words all zero.
__device__ __forceinline__ bool detect_is64(const void* ei, int tquad) {
    ulonglong2 raw = ((const ulonglong2*)ei)[tquad * 2];
    unsigned hi = (unsigned)(raw.x >> 32) | (unsigned)(raw.y >> 32);
    return __all_sync(0xffffffffu, hi == 0u);
}

// ---------------- K1: bucket-CSR fill (4 edges/thread), one pass --------------
__global__ void __launch_bounds__(256) k_fillb(const void* __restrict__ ei) {
    int t = blockIdx.x * blockDim.x + threadIdx.x;
    if (t * 4 >= N_EDGES) return;
    bool is64 = detect_is64(ei, t);
    int r0, r1, r2, r3, c0, c1, c2, c3;
    if (is64) {
        const longlong4* pr = (const longlong4*)ei;
        const longlong4* pc = (const longlong4*)((const char*)ei + (size_t)N_EDGES * 8);
        longlong4 vr = pr[t], vc = pc[t];
        r0 = (int)vr.x; r1 = (int)vr.y; r2 = (int)vr.z; r3 = (int)vr.w;
        c0 = (int)vc.x; c1 = (int)vc.y; c2 = (int)vc.z; c3 = (int)vc.w;
    } else {
        const int4* pr = (const int4*)ei;
        const int4* pc = (const int4*)((const char*)ei + (size_t)N_EDGES * 4);
        int4 vr = pr[t], vc = pc[t];
        r0 = vr.x; r1 = vr.y; r2 = vr.z; r3 = vr.w;
        c0 = vc.x; c1 = vc.y; c2 = vc.z; c3 = vc.w;
    }
    int p0 = atomicAdd(&g_cnt[c0], 1);
    int p1 = atomicAdd(&g_cnt[c1], 1);
    int p2 = atomicAdd(&g_cnt[c2], 1);
    int p3 = atomicAdd(&g_cnt[c3], 1);
    if (p0 < BUCKET) g_csr[c0 * BUCKET + p0] = r0;
    if (p1 < BUCKET) g_csr[c1 * BUCKET + p1] = r1;
    if (p2 < BUCKET) g_csr[c2 * BUCKET + p2] = r2;
    if (p3 < BUCKET) g_csr[c3 * BUCKET + p3] = r3;
}

// ---------------- K2 (side stream): GEMM1, output-split-4 --------------------
// Block: 128 threads = 32 nodes x 4 output-quarters. Thread (node, q4) computes
// outputs q4*4..q4*4+3 over full K. xs tile 32 rows x 32 k (8 KB dbl), ws tile
// 32 k x 16 (4 KB dbl). One broadcast LDS.128 of W per k per thread.
__device__ __forceinline__ void gemm1_stage(const float* __restrict__ x,
                                            const float* __restrict__ W1,
                                            unsigned xs_base, unsigned ws_base,
                                            int buf, int k0, int t, int n0) {
#pragma unroll
    for (int i = 0; i < 2; i++) {
        int f = i * 128 + t;
        int row = f >> 3, c4 = f & 7;
        int node = n0 + row;                 // grid is exact: node < N_NODES
        const float* src = x + (size_t)node * F_IN + k0 + c4 * 4;
        unsigned dst = xs_base + (unsigned)(buf * 256 + row * 8 + (c4 ^ (row & 7))) * 16u;
        asm volatile("cp.async.cg.shared.global [%0], [%1], 16;"
                     :: "r"(dst), "l"(src) : "memory");
    }
    {
        const float* srcw = W1 + (size_t)(k0 + (t >> 2)) * HIDDEN + (t & 3) * 4;
        unsigned dstw = ws_base + (unsigned)(buf * 128 + t) * 16u;
        asm volatile("cp.async.cg.shared.global [%0], [%1], 16;"
                     :: "r"(dstw), "l"(srcw) : "memory");
    }
    asm volatile("cp.async.commit_group;" ::: "memory");
}

__global__ void __launch_bounds__(128) k_gemm1(const float* __restrict__ x,
                                               const float* __restrict__ W1) {
    __shared__ __align__(16) float4 xs[2][256];   // 8 KB
    __shared__ __align__(16) float4 ws[2][128];   // 4 KB
    const int t = threadIdx.x;
    const int n0 = blockIdx.x * 32;
    const int nodeLocal = t >> 2;                 // 0..31
    const int q4 = t & 3;                         // output quarter
    const unsigned xs_base = smem_u32(&xs[0][0]);
    const unsigned ws_base = smem_u32(&ws[0][0]);

    unsigned long long acc0 = 0ull, acc1 = 0ull;  // 4 fp32 outputs

    gemm1_stage(x, W1, xs_base, ws_base, 0, 0, t, n0);

    const int rsw = nodeLocal & 7;
#pragma unroll 1
    for (int tile = 0; tile < 16; tile++) {
        int buf = tile & 1;
        if (tile < 15) {
            gemm1_stage(x, W1, xs_base, ws_base, buf ^ 1, (tile + 1) * 32, t, n0);
            asm volatile("cp.async.wait_group 1;" ::: "memory");
        } else {
            asm volatile("cp.async.wait_group 0;" ::: "memory");
        }
        __syncthreads();

#pragma unroll
        for (int kk4 = 0; kk4 < 8; kk4++) {
            float4 xv = xs[buf][nodeLocal * 8 + (kk4 ^ rsw)];
#pragma unroll
            for (int j = 0; j < 4; j++) {
                float xj = (j == 0) ? xv.x : (j == 1) ? xv.y : (j == 2) ? xv.z : xv.w;
                unsigned long long x2 = pack2(xj, xj);
                const ulonglong2* wp =
                    (const ulonglong2*)&ws[buf][(kk4 * 4 + j) * 4 + q4];
                ulonglong2 w = wp[0];
                ffma2(acc0, x2, w.x);
                ffma2(acc1, x2, w.y);
            }
        }
        __syncthreads();
    }

    int node = n0 + nodeLocal;                    // always < N_NODES (exact grid)
    float2 lo = unpack2(acc0);
    float2 hi = unpack2(acc1);
    g_hs1u[node * 4 + q4] = f4_to_h4(make_float4(lo.x, lo.y, hi.x, hi.y));
}

// ---------------- K3: hs1h = fp16(hs1u * rsqrt(deg+1)) -----------------------
__global__ void k_scale() {
    int t = blockIdx.x * blockDim.x + threadIdx.x;
    if (t >= N_NODES * 4) return;
    float d = rsqrtf((float)(g_cnt[t >> 2] + 1));
    float4 v = h4_to_f4(g_hs1u[t]);
    g_hs1h[t] = f4_to_h4(make_float4(v.x * d, v.y * d, v.z * d, v.w * d));
}

// ---------------- gather core: quad-per-node, fp16 + hadd2 pairing -----------
__device__ __forceinline__ float4 gather_acc(const uint2* __restrict__ src,
                                             int beg, int end, int q,
                                             unsigned qmask, int qbase) {
    const int* __restrict__ csr = g_csr;
    float4 acc = make_float4(0.f, 0.f, 0.f, 0.f);
    int e = beg;
    if (e + 8 <= end) {
        int ia = csr[e + 2 * q];
        int ib = csr[e + 2 * q + 1];
        for (; e + 8 <= end; ) {
            int e2 = e + 8;
            int na = 0, nb = 0;
            if (e2 + 8 <= end) {                 // prefetch next iter's indices
                na = csr[e2 + 2 * q];
                nb = csr[e2 + 2 * q + 1];
            }
            int r0 = __shfl_sync(qmask, ia, qbase + 0);
            int r1 = __shfl_sync(qmask, ib, qbase + 0);
            int r2 = __shfl_sync(qmask, ia, qbase + 1);
            int r3 = __shfl_sync(qmask, ib, qbase + 1);
            int r4 = __shfl_sync(qmask, ia, qbase + 2);
            int r5 = __shfl_sync(qmask, ib, qbase + 2);
            int r6 = __shfl_sync(qmask, ia, qbase + 3);
            int r7 = __shfl_sync(qmask, ib, qbase + 3);
            uint2 u0 = src[r0 * 4 + q];
            uint2 u1 = src[r1 * 4 + q];
            uint2 u2 = src[r2 * 4 + q];
            uint2 u3 = src[r3 * 4 + q];
            uint2 u4 = src[r4 * 4 + q];
            uint2 u5 = src[r5 * 4 + q];
            uint2 u6 = src[r6 * 4 + q];
            uint2 u7 = src[r7 * 4 + q];
            uint2 p01 = h4add(u0, u1);
            uint2 p23 = h4add(u2, u3);
            uint2 p45 = h4add(u4, u5);
            uint2 p67 = h4add(u6, u7);
            f4acc(acc, h4_to_f4(p01)); f4acc(acc, h4_to_f4(p23));
            f4acc(acc, h4_to_f4(p45)); f4acc(acc, h4_to_f4(p67));
            ia = na; ib = nb; e = e2;
        }
    }
    if (e + 4 <= end) {
        int myi = csr[e + q];
        int r0 = __shfl_sync(qmask, myi, qbase + 0);
        int r1 = __shfl_sync(qmask, myi, qbase + 1);
        int r2 = __shfl_sync(qmask, myi, qbase + 2);
        int r3 = __shfl_sync(qmask, myi, qbase + 3);
        uint2 u0 = src[r0 * 4 + q];
        uint2 u1 = src[r1 * 4 + q];
        uint2 u2 = src[r2 * 4 + q];
        uint2 u3 = src[r3 * 4 + q];
        uint2 p01 = h4add(u0, u1);
        uint2 p23 = h4add(u2, u3);
        f4acc(acc, h4_to_f4(p01)); f4acc(acc, h4_to_f4(p23));
        e += 4;
    }
    int rem = end - e;
    if (rem > 0) {
        int myi = (q < rem) ? csr[e + q] : 0;
        for (int j = 0; j < rem; j++) {
            int r = __shfl_sync(qmask, myi, qbase + j);
            f4acc(acc, h4_to_f4(src[r * 4 + q]));
        }
    }
    return acc;
}

// ---------------- K4: layer1 gather + relu -----------------------------------
__global__ void __launch_bounds__(256) k_gather1(const float* __restrict__ b1) {
    int t = blockIdx.x * blockDim.x + threadIdx.x;
    int node = t >> 2;
    if (node >= N_NODES) return;
    int q = t & 3;
    int qbase = (threadIdx.x & 31) & ~3;
    unsigned qmask = 0xFu << qbase;
    int cnt = g_cnt[node];
    float d = rsqrtf((float)(cnt + 1));
    if (cnt > BUCKET) cnt = BUCKET;
    int beg = node * BUCKET;
    int end = beg + cnt;
    float4 acc = gather_acc(g_hs1h, beg, end, q, qmask, qbase);
    float4 self = h4_to_f4(g_hs1h[node * 4 + q]);
    float4 bb = ((const float4*)b1)[q];
    float4 h;
    h.x = fmaxf(fmaf(acc.x + self.x, d, bb.x), 0.f) * d;
    h.y = fmaxf(fmaf(acc.y + self.y, d, bb.y), 0.f) * d;
    h.z = fmaxf(fmaf(acc.z + self.z, d, bb.z), 0.f) * d;
    h.w = fmaxf(fmaf(acc.w + self.w, d, bb.w), 0.f) * d;
    g_hs2h[node * 4 + q] = f4_to_h4(h);
}

// ---------------- K5: layer2 gather fused @W2 + b2 -> out; cleans g_cnt ------
__global__ void __launch_bounds__(256) k_gather2(const float* __restrict__ W2,
                                                 const float* __restrict__ b2,
                                                 float* __restrict__ out) {
    __shared__ float w2s[HIDDEN * N_CLASSES];
    __shared__ float b2s[N_CLASSES];
    {
        int tt = threadIdx.x;
        for (int i = tt; i < HIDDEN * N_CLASSES; i += 256) w2s[i] = W2[i];
        if (tt < N_CLASSES) b2s[tt] = b2[tt];
        __syncthreads();
    }
    int t = blockIdx.x * blockDim.x + threadIdx.x;
    int node = t >> 2;
    bool valid = (node < N_NODES);
    int node_c = valid ? node : 0;
    int q = t & 3;
    int lane = threadIdx.x & 31;
    int qbase = lane & ~3;
    unsigned qmask = 0xFu << qbase;

    int cnt = valid ? g_cnt[node_c] : 0;     // invalid quads don't touch g_cnt
    float d = rsqrtf((float)(cnt + 1));
    if (valid && q == 0) g_cnt[node_c] = 0;  // self-clean for next replay
    if (cnt > BUCKET) cnt = BUCKET;
    int beg = node_c * BUCKET;
    int end = beg + cnt;
    float4 acc = gather_acc(g_hs2h, beg, end, q, qmask, qbase);
    float4 self = h4_to_f4(g_hs2h[node_c * 4 + q]);
    float av[4];
    av[0] = (acc.x + self.x) * d;
    av[1] = (acc.y + self.y) * d;
    av[2] = (acc.z + self.z) * d;
    av[3] = (acc.w + self.w) * d;

    float o[10];
#pragma unroll
    for (int j = 0; j < 10; j++) o[j] = b2s[q + 4 * j];

#pragma unroll
    for (int p = 0; p < 4; p++) {
#pragma unroll
        for (int comp = 0; comp < 4; comp++) {
            float v = __shfl_sync(0xffffffffu, av[comp], qbase + p);
            int k = p * 4 + comp;
#pragma unroll
            for (int j = 0; j < 10; j++)
                o[j] = fmaf(v, w2s[k * N_CLASSES + q + 4 * j], o[j]);
        }
    }
    if (valid) {
#pragma unroll
        for (int j = 0; j < 10; j++)
            out[node * N_CLASSES + q + 4 * j] = o[j];
    }
}

// ---------------- launch: 5 kernels; fillb overlaps gemm1 --------------------
extern "C" void kernel_launch(void* const* d_in, const int* in_sizes, int n_in,
                              void* d_out, int out_size) {
    const float* x  = (const float*)d_in[0];
    const void*  ei = d_in[1];
    const float* W1 = (const float*)d_in[2];
    const float* b1 = (const float*)d_in[3];
    const float* W2 = (const float*)d_in[4];
    const float* b2 = (const float*)d_in[5];
    float* out = (float*)d_out;

    // fork: GEMM1 on a side stream (independent of edge processing)
    cudaStream_t s2;
    cudaStreamCreateWithFlags(&s2, cudaStreamNonBlocking);
    cudaEvent_t evA, evB;
    cudaEventCreateWithFlags(&evA, cudaEventDisableTiming);
    cudaEventCreateWithFlags(&evB, cudaEventDisableTiming);
    cudaEventRecord(evA, 0);
    cudaStreamWaitEvent(s2, evA, 0);
    k_gemm1<<<N_NODES / 32, 128, 0, s2>>>(x, W1);   // 3125 blocks, exact
    cudaEventRecord(evB, s2);

    // main stream: single-pass bucket CSR build (overlaps gemm1)
    k_fillb<<<(N_EDGES / 4 + 255) / 256, 256>>>(ei);

    // join, then scale + gathers
    cudaStreamWaitEvent(0, evB, 0);
    k_scale<<<(N_NODES * 4 + 255) / 256, 256>>>();
    k_gather1<<<(N_NODES * 4 + 255) / 256, 256>>>(b1);
    k_gather2<<<(N_NODES * 4 + 255) / 256, 256>>>(W2, b2, out);

    cudaEventDestroy(evA);
    cudaEventDestroy(evB);
    cudaStreamDestroy(s2);
}

// round 13
// speedup vs baseline: 1.1973x; 1.1973x over previous
#include <cuda_runtime.h>
#include <cuda_fp16.h>

#define N_NODES 100000
#define N_EDGES 1600000
#define F_IN 512
#define HIDDEN 16
#define N_CLASSES 40
#define BUCKET 128                     // CSR slots per node (P(deg>128) ~ 1e-60)

// ---------------- scratch (no device allocs; zero at module load) ------------
__device__ int   g_csr [N_NODES * BUCKET];   // bucket CSR: sources of in-edges
__device__ int   g_cnt [N_NODES];            // in-degree/cursor (self-cleaned by k_gather2)
__device__ uint2 g_hs1h[N_NODES * 4];        // (x@W1)*dis as fp16
__device__ uint2 g_hs2h[N_NODES * 4];        // relu(...)*dis as fp16

// ---------------- helpers ----------------
__device__ __forceinline__ unsigned long long pack2(float x, float y) {
    unsigned long long r;
    asm("mov.b64 %0, {%1,%2};" : "=l"(r) : "f"(x), "f"(y));
    return r;
}
__device__ __forceinline__ float2 unpack2(unsigned long long v) {
    float2 f;
    asm("mov.b64 {%0,%1}, %2;" : "=f"(f.x), "=f"(f.y) : "l"(v));
    return f;
}
__device__ __forceinline__ void ffma2(unsigned long long& d,
                                      unsigned long long a,
                                      unsigned long long b) {
    asm("fma.rn.f32x2 %0, %1, %2, %0;" : "+l"(d) : "l"(a), "l"(b));
}
__device__ __forceinline__ unsigned smem_u32(const void* p) {
    return (unsigned)__cvta_generic_to_shared(p);
}
__device__ __forceinline__ float4 h4_to_f4(uint2 u) {
    __half2 a = *reinterpret_cast<__half2*>(&u.x);
    __half2 b = *reinterpret_cast<__half2*>(&u.y);
    float2 fa = __half22float2(a), fb = __half22float2(b);
    return make_float4(fa.x, fa.y, fb.x, fb.y);
}
__device__ __forceinline__ uint2 f4_to_h4(float4 v) {
    __half2 a = __floats2half2_rn(v.x, v.y);
    __half2 b = __floats2half2_rn(v.z, v.w);
    uint2 u;
    u.x = *reinterpret_cast<unsigned*>(&a);
    u.y = *reinterpret_cast<unsigned*>(&b);
    return u;
}
// fp16 pairwise add of two packed-4-half values
__device__ __forceinline__ uint2 h4add(uint2 a, uint2 b) {
    __half2 ax = *reinterpret_cast<__half2*>(&a.x);
    __half2 ay = *reinterpret_cast<__half2*>(&a.y);
    __half2 bx = *reinterpret_cast<__half2*>(&b.x);
    __half2 by = *reinterpret_cast<__half2*>(&b.y);
    __half2 cx = __hadd2(ax, bx);
    __half2 cy = __hadd2(ay, by);
    uint2 c;
    c.x = *reinterpret_cast<unsigned*>(&cx);
    c.y = *reinterpret_cast<unsigned*>(&cy);
    return c;
}
__device__ __forceinline__ void f4acc(float4& a, float4 b) {
    a.x += b.x; a.y += b.y; a.z += b.z; a.w += b.w;
}

// Per-warp dtype detect: int64 (<2^31) => hi 32-bit words all zero.
__device__ __forceinline__ bool detect_is64(const void* ei, int tquad) {
    ulonglong2 raw = ((const ulonglong2*)ei)[tquad * 2];
    unsigned hi = (unsigned)(raw.x >> 32) | (unsigned)(raw.y >> 32);
    return __all_sync(0xffffffffu, hi == 0u);
}

// ---------------- K1: bucket-CSR fill (4 edges/thread), one pass --------------
__global__ void __launch_bounds__(256) k_fillb(const void* __restrict__ ei) {
    int t = blockIdx.x * blockDim.x + threadIdx.x;
    if (t * 4 >= N_EDGES) return;
    bool is64 = detect_is64(ei, t);
    int r0, r1, r2, r3, c0, c1, c2, c3;
    if (is64) {
        const longlong4* pr = (const longlong4*)ei;
        const longlong4* pc = (const longlong4*)((const char*)ei + (size_t)N_EDGES * 8);
        longlong4 vr = pr[t], vc = pc[t];
        r0 = (int)vr.x; r1 = (int)vr.y; r2 = (int)vr.z; r3 = (int)vr.w;
        c0 = (int)vc.x; c1 = (int)vc.y; c2 = (int)vc.z; c3 = (int)vc.w;
    } else {
        const int4* pr = (const int4*)ei;
        const int4* pc = (const int4*)((const char*)ei + (size_t)N_EDGES * 4);
        int4 vr = pr[t], vc = pc[t];
        r0 = vr.x; r1 = vr.y; r2 = vr.z; r3 = vr.w;
        c0 = vc.x; c1 = vc.y; c2 = vc.z; c3 = vc.w;
    }
    int p0 = atomicAdd(&g_cnt[c0], 1);
    int p1 = atomicAdd(&g_cnt[c1], 1);
    int p2 = atomicAdd(&g_cnt[c2], 1);
    int p3 = atomicAdd(&g_cnt[c3], 1);
    if (p0 < BUCKET) g_csr[c0 * BUCKET + p0] = r0;
    if (p1 < BUCKET) g_csr[c1 * BUCKET + p1] = r1;
    if (p2 < BUCKET) g_csr[c2 * BUCKET + p2] = r2;
    if (p3 < BUCKET) g_csr[c3 * BUCKET + p3] = r3;
}

// ---------------- K2: GEMM1 + fused dis-scale (runs after fillb) -------------
// R11-proven core: 128 threads = 128 nodes, cp.async double-buffered,
// XOR-swizzled x tile, FFMA2 inner loop. Epilogue multiplies by
// rsqrt(deg+1) (g_cnt valid: fillb completed) and stores fp16 directly.
__device__ __forceinline__ void gemm1_stage(const float* __restrict__ x,
                                            const float* __restrict__ W1,
                                            unsigned xs_base, unsigned ws_base,
                                            int buf, int k0, int t, int n0) {
#pragma unroll
    for (int i = 0; i < 8; i++) {
        int f = i * 128 + t;
        int row = f >> 3, c4 = f & 7;
        int node = n0 + row;
        const float* src = x + (size_t)node * F_IN + k0 + c4 * 4;
        unsigned dst = xs_base + (unsigned)(buf * 1024 + row * 8 + (c4 ^ (row & 7))) * 16u;
        int sb = (node < N_NODES) ? 16 : 0;
        asm volatile("cp.async.cg.shared.global [%0], [%1], 16, %2;"
                     :: "r"(dst), "l"(src), "r"(sb) : "memory");
    }
    {
        const float* srcw = W1 + (size_t)(k0 + (t >> 2)) * HIDDEN + (t & 3) * 4;
        unsigned dstw = ws_base + (unsigned)(buf * 128 + t) * 16u;
        asm volatile("cp.async.cg.shared.global [%0], [%1], 16;"
                     :: "r"(dstw), "l"(srcw) : "memory");
    }
    asm volatile("cp.async.commit_group;" ::: "memory");
}

__global__ void __launch_bounds__(128) k_gemm1(const float* __restrict__ x,
                                               const float* __restrict__ W1) {
    __shared__ __align__(16) float4 xs[2][1024];   // 32 KB
    __shared__ __align__(16) float4 ws[2][128];    // 4 KB
    const int t = threadIdx.x;
    const int n0 = blockIdx.x * 128;
    const unsigned xs_base = smem_u32(&xs[0][0]);
    const unsigned ws_base = smem_u32(&ws[0][0]);

    unsigned long long acc[8];
#pragma unroll
    for (int p = 0; p < 8; p++) acc[p] = 0ull;

    gemm1_stage(x, W1, xs_base, ws_base, 0, 0, t, n0);

    const int tsw = t & 7;
#pragma unroll 1
    for (int tile = 0; tile < 16; tile++) {
        int buf = tile & 1;
        if (tile < 15) {
            gemm1_stage(x, W1, xs_base, ws_base, buf ^ 1, (tile + 1) * 32, t, n0);
            asm volatile("cp.async.wait_group 1;" ::: "memory");
        } else {
            asm volatile("cp.async.wait_group 0;" ::: "memory");
        }
        __syncthreads();

#pragma unroll
        for (int kk4 = 0; kk4 < 8; kk4++) {
            float4 xv = xs[buf][t * 8 + (kk4 ^ tsw)];
#pragma unroll
            for (int j = 0; j < 4; j++) {
                float xj = (j == 0) ? xv.x : (j == 1) ? xv.y : (j == 2) ? xv.z : xv.w;
                unsigned long long x2 = pack2(xj, xj);
                const ulonglong2* wp =
                    (const ulonglong2*)&ws[buf][(kk4 * 4 + j) * 4];
                ulonglong2 w0 = wp[0], w1 = wp[1], w2 = wp[2], w3 = wp[3];
                ffma2(acc[0], x2, w0.x); ffma2(acc[1], x2, w0.y);
                ffma2(acc[2], x2, w1.x); ffma2(acc[3], x2, w1.y);
                ffma2(acc[4], x2, w2.x); ffma2(acc[5], x2, w2.y);
                ffma2(acc[6], x2, w3.x); ffma2(acc[7], x2, w3.y);
            }
        }
        __syncthreads();
    }

    int node = n0 + t;
    if (node < N_NODES) {
        float d = rsqrtf((float)(g_cnt[node] + 1));   // fused k_scale
#pragma unroll
        for (int p = 0; p < 4; p++) {
            float2 lo = unpack2(acc[2 * p]);
            float2 hi = unpack2(acc[2 * p + 1]);
            g_hs1h[node * 4 + p] =
                f4_to_h4(make_float4(lo.x * d, lo.y * d, hi.x * d, hi.y * d));
        }
    }
}

// ---------------- gather core: quad-per-node, fp16 + hadd2 pairing -----------
__device__ __forceinline__ float4 gather_acc(const uint2* __restrict__ src,
                                             int beg, int end, int q,
                                             unsigned qmask, int qbase) {
    const int* __restrict__ csr = g_csr;
    float4 acc = make_float4(0.f, 0.f, 0.f, 0.f);
    int e = beg;
    if (e + 8 <= end) {
        int ia = csr[e + 2 * q];
        int ib = csr[e + 2 * q + 1];
        for (; e + 8 <= end; ) {
            int e2 = e + 8;
            int na = 0, nb = 0;
            if (e2 + 8 <= end) {                 // prefetch next iter's indices
                na = csr[e2 + 2 * q];
                nb = csr[e2 + 2 * q + 1];
            }
            int r0 = __shfl_sync(qmask, ia, qbase + 0);
            int r1 = __shfl_sync(qmask, ib, qbase + 0);
            int r2 = __shfl_sync(qmask, ia, qbase + 1);
            int r3 = __shfl_sync(qmask, ib, qbase + 1);
            int r4 = __shfl_sync(qmask, ia, qbase + 2);
            int r5 = __shfl_sync(qmask, ib, qbase + 2);
            int r6 = __shfl_sync(qmask, ia, qbase + 3);
            int r7 = __shfl_sync(qmask, ib, qbase + 3);
            uint2 u0 = src[r0 * 4 + q];
            uint2 u1 = src[r1 * 4 + q];
            uint2 u2 = src[r2 * 4 + q];
            uint2 u3 = src[r3 * 4 + q];
            uint2 u4 = src[r4 * 4 + q];
            uint2 u5 = src[r5 * 4 + q];
            uint2 u6 = src[r6 * 4 + q];
            uint2 u7 = src[r7 * 4 + q];
            uint2 p01 = h4add(u0, u1);
            uint2 p23 = h4add(u2, u3);
            uint2 p45 = h4add(u4, u5);
            uint2 p67 = h4add(u6, u7);
            f4acc(acc, h4_to_f4(p01)); f4acc(acc, h4_to_f4(p23));
            f4acc(acc, h4_to_f4(p45)); f4acc(acc, h4_to_f4(p67));
            ia = na; ib = nb; e = e2;
        }
    }
    if (e + 4 <= end) {
        int myi = csr[e + q];
        int r0 = __shfl_sync(qmask, myi, qbase + 0);
        int r1 = __shfl_sync(qmask, myi, qbase + 1);
        int r2 = __shfl_sync(qmask, myi, qbase + 2);
        int r3 = __shfl_sync(qmask, myi, qbase + 3);
        uint2 u0 = src[r0 * 4 + q];
        uint2 u1 = src[r1 * 4 + q];
        uint2 u2 = src[r2 * 4 + q];
        uint2 u3 = src[r3 * 4 + q];
        uint2 p01 = h4add(u0, u1);
        uint2 p23 = h4add(u2, u3);
        f4acc(acc, h4_to_f4(p01)); f4acc(acc, h4_to_f4(p23));
        e += 4;
    }
    int rem = end - e;
    if (rem > 0) {
        int myi = (q < rem) ? csr[e + q] : 0;
        for (int j = 0; j < rem; j++) {
            int r = __shfl_sync(qmask, myi, qbase + j);
            f4acc(acc, h4_to_f4(src[r * 4 + q]));
        }
    }
    return acc;
}

// ---------------- K3: layer1 gather + relu -----------------------------------
__global__ void __launch_bounds__(256) k_gather1(const float* __restrict__ b1) {
    int t = blockIdx.x * blockDim.x + threadIdx.x;
    int node = t >> 2;
    if (node >= N_NODES) return;
    int q = t & 3;
    int qbase = (threadIdx.x & 31) & ~3;
    unsigned qmask = 0xFu << qbase;
    int cnt = g_cnt[node];
    float d = rsqrtf((float)(cnt + 1));
    if (cnt > BUCKET) cnt = BUCKET;
    int beg = node * BUCKET;
    int end = beg + cnt;
    float4 acc = gather_acc(g_hs1h, beg, end, q, qmask, qbase);
    float4 self = h4_to_f4(g_hs1h[node * 4 + q]);
    float4 bb = ((const float4*)b1)[q];
    float4 h;
    h.x = fmaxf(fmaf(acc.x + self.x, d, bb.x), 0.f) * d;
    h.y = fmaxf(fmaf(acc.y + self.y, d, bb.y), 0.f) * d;
    h.z = fmaxf(fmaf(acc.z + self.z, d, bb.z), 0.f) * d;
    h.w = fmaxf(fmaf(acc.w + self.w, d, bb.w), 0.f) * d;
    g_hs2h[node * 4 + q] = f4_to_h4(h);
}

// ---------------- K4: layer2 gather fused @W2 + b2 -> out; cleans g_cnt ------
__global__ void __launch_bounds__(256) k_gather2(const float* __restrict__ W2,
                                                 const float* __restrict__ b2,
                                                 float* __restrict__ out) {
    __shared__ float w2s[HIDDEN * N_CLASSES];
    __shared__ float b2s[N_CLASSES];
    {
        int tt = threadIdx.x;
        for (int i = tt; i < HIDDEN * N_CLASSES; i += 256) w2s[i] = W2[i];
        if (tt < N_CLASSES) b2s[tt] = b2[tt];
        __syncthreads();
    }
    int t = blockIdx.x * blockDim.x + threadIdx.x;
    int node = t >> 2;
    bool valid = (node < N_NODES);
    int node_c = valid ? node : 0;
    int q = t & 3;
    int lane = threadIdx.x & 31;
    int qbase = lane & ~3;
    unsigned qmask = 0xFu << qbase;

    int cnt = valid ? g_cnt[node_c] : 0;     // invalid quads don't touch g_cnt
    float d = rsqrtf((float)(cnt + 1));
    if (valid && q == 0) g_cnt[node_c] = 0;  // self-clean for next replay
    if (cnt > BUCKET) cnt = BUCKET;
    int beg = node_c * BUCKET;
    int end = beg + cnt;
    float4 acc = gather_acc(g_hs2h, beg, end, q, qmask, qbase);
    float4 self = h4_to_f4(g_hs2h[node_c * 4 + q]);
    float av[4];
    av[0] = (acc.x + self.x) * d;
    av[1] = (acc.y + self.y) * d;
    av[2] = (acc.z + self.z) * d;
    av[3] = (acc.w + self.w) * d;

    float o[10];
#pragma unroll
    for (int j = 0; j < 10; j++) o[j] = b2s[q + 4 * j];

#pragma unroll
    for (int p = 0; p < 4; p++) {
#pragma unroll
        for (int comp = 0; comp < 4; comp++) {
            float v = __shfl_sync(0xffffffffu, av[comp], qbase + p);
            int k = p * 4 + comp;
#pragma unroll
            for (int j = 0; j < 10; j++)
                o[j] = fmaf(v, w2s[k * N_CLASSES + q + 4 * j], o[j]);
        }
    }
    if (valid) {
#pragma unroll
        for (int j = 0; j < 10; j++)
            out[node * N_CLASSES + q + 4 * j] = o[j];
    }
}

// ---------------- launch: 4 kernels, single stream ---------------------------
extern "C" void kernel_launch(void* const* d_in, const int* in_sizes, int n_in,
                              void* d_out, int out_size) {
    const float* x  = (const float*)d_in[0];
    const void*  ei = d_in[1];
    const float* W1 = (const float*)d_in[2];
    const float* b1 = (const float*)d_in[3];
    const float* W2 = (const float*)d_in[4];
    const float* b2 = (const float*)d_in[5];
    float* out = (float*)d_out;

    // memory-bound phases don't overlap (shared DRAM/LTS) — run serial, which
    // lets gemm1 fuse the dis-scaling (g_cnt is final after fillb).
    k_fillb<<<(N_EDGES / 4 + 255) / 256, 256>>>(ei);
    k_gemm1<<<(N_NODES + 127) / 128, 128>>>(x, W1);
    k_gather1<<<(N_NODES * 4 + 255) / 256, 256>>>(b1);
    k_gather2<<<(N_NODES * 4 + 255) / 256, 256>>>(W2, b2, out);
}

// round 14
// speedup vs baseline: 1.2851x; 1.0734x over previous
#include <cuda_runtime.h>
#include <cuda_fp16.h>

#define N_NODES 100000
#define N_EDGES 1600000
#define F_IN 512
#define HIDDEN 16
#define N_CLASSES 40
#define BUCKET 128                     // CSR slots per node (P(deg>128) ~ 1e-60)

// ---------------- scratch (no device allocs; zero at module load) ------------
__device__ int   g_csr [N_NODES * BUCKET];   // bucket CSR: sources of in-edges
__device__ int   g_cnt [N_NODES];            // in-degree/cursor (self-cleaned by k_gather2)
__device__ uint2 g_hs1u[N_NODES * 4];        // x@W1 as fp16 (unscaled, gemm1 out)
__device__ uint2 g_hs1h[N_NODES * 4];        // (x@W1)*dis as fp16
__device__ uint2 g_hs2h[N_NODES * 4];        // relu(...)*dis as fp16

// ---------------- helpers ----------------
__device__ __forceinline__ unsigned long long pack2(float x, float y) {
    unsigned long long r;
    asm("mov.b64 %0, {%1,%2};" : "=l"(r) : "f"(x), "f"(y));
    return r;
}
__device__ __forceinline__ float2 unpack2(unsigned long long v) {
    float2 f;
    asm("mov.b64 {%0,%1}, %2;" : "=f"(f.x), "=f"(f.y) : "l"(v));
    return f;
}
__device__ __forceinline__ void ffma2(unsigned long long& d,
                                      unsigned long long a,
                                      unsigned long long b) {
    asm("fma.rn.f32x2 %0, %1, %2, %0;" : "+l"(d) : "l"(a), "l"(b));
}
__device__ __forceinline__ unsigned smem_u32(const void* p) {
    return (unsigned)__cvta_generic_to_shared(p);
}
__device__ __forceinline__ float4 h4_to_f4(uint2 u) {
    __half2 a = *reinterpret_cast<__half2*>(&u.x);
    __half2 b = *reinterpret_cast<__half2*>(&u.y);
    float2 fa = __half22float2(a), fb = __half22float2(b);
    return make_float4(fa.x, fa.y, fb.x, fb.y);
}
__device__ __forceinline__ uint2 f4_to_h4(float4 v) {
    __half2 a = __floats2half2_rn(v.x, v.y);
    __half2 b = __floats2half2_rn(v.z, v.w);
    uint2 u;
    u.x = *reinterpret_cast<unsigned*>(&a);
    u.y = *reinterpret_cast<unsigned*>(&b);
    return u;
}
// fp16 pairwise add of two packed-4-half values
__device__ __forceinline__ uint2 h4add(uint2 a, uint2 b) {
    __half2 ax = *reinterpret_cast<__half2*>(&a.x);
    __half2 ay = *reinterpret_cast<__half2*>(&a.y);
    __half2 bx = *reinterpret_cast<__half2*>(&b.x);
    __half2 by = *reinterpret_cast<__half2*>(&b.y);
    __half2 cx = __hadd2(ax, bx);
    __half2 cy = __hadd2(ay, by);
    uint2 c;
    c.x = *reinterpret_cast<unsigned*>(&cx);
    c.y = *reinterpret_cast<unsigned*>(&cy);
    return c;
}
__device__ __forceinline__ void f4acc(float4& a, float4 b) {
    a.x += b.x; a.y += b.y; a.z += b.z; a.w += b.w;
}

// Per-warp dtype detect: int64 (<2^31) => hi 32-bit words all zero.
__device__ __forceinline__ bool detect_is64(const void* ei, int tquad) {
    ulonglong2 raw = ((const ulonglong2*)ei)[tquad * 2];
    unsigned hi = (unsigned)(raw.x >> 32) | (unsigned)(raw.y >> 32);
    return __all_sync(0xffffffffu, hi == 0u);
}

// ---------------- K1: bucket-CSR fill (4 edges/thread), one pass --------------
__global__ void __launch_bounds__(256) k_fillb(const void* __restrict__ ei) {
    int t = blockIdx.x * blockDim.x + threadIdx.x;
    if (t * 4 >= N_EDGES) return;
    bool is64 = detect_is64(ei, t);
    int r0, r1, r2, r3, c0, c1, c2, c3;
    if (is64) {
        const longlong4* pr = (const longlong4*)ei;
        const longlong4* pc = (const longlong4*)((const char*)ei + (size_t)N_EDGES * 8);
        longlong4 vr = pr[t], vc = pc[t];
        r0 = (int)vr.x; r1 = (int)vr.y; r2 = (int)vr.z; r3 = (int)vr.w;
        c0 = (int)vc.x; c1 = (int)vc.y; c2 = (int)vc.z; c3 = (int)vc.w;
    } else {
        const int4* pr = (const int4*)ei;
        const int4* pc = (const int4*)((const char*)ei + (size_t)N_EDGES * 4);
        int4 vr = pr[t], vc = pc[t];
        r0 = vr.x; r1 = vr.y; r2 = vr.z; r3 = vr.w;
        c0 = vc.x; c1 = vc.y; c2 = vc.z; c3 = vc.w;
    }
    int p0 = atomicAdd(&g_cnt[c0], 1);
    int p1 = atomicAdd(&g_cnt[c1], 1);
    int p2 = atomicAdd(&g_cnt[c2], 1);
    int p3 = atomicAdd(&g_cnt[c3], 1);
    if (p0 < BUCKET) g_csr[c0 * BUCKET + p0] = r0;
    if (p1 < BUCKET) g_csr[c1 * BUCKET + p1] = r1;
    if (p2 < BUCKET) g_csr[c2 * BUCKET + p2] = r2;
    if (p3 < BUCKET) g_csr[c3 * BUCKET + p3] = r3;
}

// ---------------- K2 (side stream): GEMM1, cp.async double-buffered ----------
__device__ __forceinline__ void gemm1_stage(const float* __restrict__ x,
                                            const float* __restrict__ W1,
                                            unsigned xs_base, unsigned ws_base,
                                            int buf, int k0, int t, int n0) {
#pragma unroll
    for (int i = 0; i < 8; i++) {
        int f = i * 128 + t;
        int row = f >> 3, c4 = f & 7;
        int node = n0 + row;
        const float* src = x + (size_t)node * F_IN + k0 + c4 * 4;
        unsigned dst = xs_base + (unsigned)(buf * 1024 + row * 8 + (c4 ^ (row & 7))) * 16u;
        int sb = (node < N_NODES) ? 16 : 0;
        asm volatile("cp.async.cg.shared.global [%0], [%1], 16, %2;"
                     :: "r"(dst), "l"(src), "r"(sb) : "memory");
    }
    {
        const float* srcw = W1 + (size_t)(k0 + (t >> 2)) * HIDDEN + (t & 3) * 4;
        unsigned dstw = ws_base + (unsigned)(buf * 128 + t) * 16u;
        asm volatile("cp.async.cg.shared.global [%0], [%1], 16;"
                     :: "r"(dstw), "l"(srcw) : "memory");
    }
    asm volatile("cp.async.commit_group;" ::: "memory");
}

__global__ void __launch_bounds__(128) k_gemm1(const float* __restrict__ x,
                                               const float* __restrict__ W1) {
    __shared__ __align__(16) float4 xs[2][1024];   // 32 KB
    __shared__ __align__(16) float4 ws[2][128];    // 4 KB
    const int t = threadIdx.x;
    const int n0 = blockIdx.x * 128;
    const unsigned xs_base = smem_u32(&xs[0][0]);
    const unsigned ws_base = smem_u32(&ws[0][0]);

    unsigned long long acc[8];
#pragma unroll
    for (int p = 0; p < 8; p++) acc[p] = 0ull;

    gemm1_stage(x, W1, xs_base, ws_base, 0, 0, t, n0);

    const int tsw = t & 7;
#pragma unroll 1
    for (int tile = 0; tile < 16; tile++) {
        int buf = tile & 1;
        if (tile < 15) {
            gemm1_stage(x, W1, xs_base, ws_base, buf ^ 1, (tile + 1) * 32, t, n0);
            asm volatile("cp.async.wait_group 1;" ::: "memory");
        } else {
            asm volatile("cp.async.wait_group 0;" ::: "memory");
        }
        __syncthreads();

#pragma unroll
        for (int kk4 = 0; kk4 < 8; kk4++) {
            float4 xv = xs[buf][t * 8 + (kk4 ^ tsw)];
#pragma unroll
            for (int j = 0; j < 4; j++) {
                float xj = (j == 0) ? xv.x : (j == 1) ? xv.y : (j == 2) ? xv.z : xv.w;
                unsigned long long x2 = pack2(xj, xj);
                const ulonglong2* wp =
                    (const ulonglong2*)&ws[buf][(kk4 * 4 + j) * 4];
                ulonglong2 w0 = wp[0], w1 = wp[1], w2 = wp[2], w3 = wp[3];
                ffma2(acc[0], x2, w0.x); ffma2(acc[1], x2, w0.y);
                ffma2(acc[2], x2, w1.x); ffma2(acc[3], x2, w1.y);
                ffma2(acc[4], x2, w2.x); ffma2(acc[5], x2, w2.y);
                ffma2(acc[6], x2, w3.x); ffma2(acc[7], x2, w3.y);
            }
        }
        __syncthreads();
    }

    int node = n0 + t;
    if (node < N_NODES) {
#pragma unroll
        for (int p = 0; p < 4; p++) {
            float2 lo = unpack2(acc[2 * p]);
            float2 hi = unpack2(acc[2 * p + 1]);
            g_hs1u[node * 4 + p] = f4_to_h4(make_float4(lo.x, lo.y, hi.x, hi.y));
        }
    }
}

// ---------------- K3: hs1h = fp16(hs1u * rsqrt(deg+1)) -----------------------
__global__ void k_scale() {
    int t = blockIdx.x * blockDim.x + threadIdx.x;
    if (t >= N_NODES * 4) return;
    float d = rsqrtf((float)(g_cnt[t >> 2] + 1));
    float4 v = h4_to_f4(g_hs1u[t]);
    g_hs1h[t] = f4_to_h4(make_float4(v.x * d, v.y * d, v.z * d, v.w * d));
}

// ---------------- gather core: quad-per-node, fp16 + hadd2 pairing -----------
__device__ __forceinline__ float4 gather_acc(const uint2* __restrict__ src,
                                             int beg, int end, int q,
                                             unsigned qmask, int qbase) {
    const int* __restrict__ csr = g_csr;
    float4 acc = make_float4(0.f, 0.f, 0.f, 0.f);
    int e = beg;
    if (e + 8 <= end) {
        int ia = csr[e + 2 * q];
        int ib = csr[e + 2 * q + 1];
        for (; e + 8 <= end; ) {
            int e2 = e + 8;
            int na = 0, nb = 0;
            if (e2 + 8 <= end) {                 // prefetch next iter's indices
                na = csr[e2 + 2 * q];
                nb = csr[e2 + 2 * q + 1];
            }
            int r0 = __shfl_sync(qmask, ia, qbase + 0);
            int r1 = __shfl_sync(qmask, ib, qbase + 0);
            int r2 = __shfl_sync(qmask, ia, qbase + 1);
            int r3 = __shfl_sync(qmask, ib, qbase + 1);
            int r4 = __shfl_sync(qmask, ia, qbase + 2);
            int r5 = __shfl_sync(qmask, ib, qbase + 2);
            int r6 = __shfl_sync(qmask, ia, qbase + 3);
            int r7 = __shfl_sync(qmask, ib, qbase + 3);
            uint2 u0 = src[r0 * 4 + q];
            uint2 u1 = src[r1 * 4 + q];
            uint2 u2 = src[r2 * 4 + q];
            uint2 u3 = src[r3 * 4 + q];
            uint2 u4 = src[r4 * 4 + q];
            uint2 u5 = src[r5 * 4 + q];
            uint2 u6 = src[r6 * 4 + q];
            uint2 u7 = src[r7 * 4 + q];
            uint2 p01 = h4add(u0, u1);
            uint2 p23 = h4add(u2, u3);
            uint2 p45 = h4add(u4, u5);
            uint2 p67 = h4add(u6, u7);
            f4acc(acc, h4_to_f4(p01)); f4acc(acc, h4_to_f4(p23));
            f4acc(acc, h4_to_f4(p45)); f4acc(acc, h4_to_f4(p67));
            ia = na; ib = nb; e = e2;
        }
    }
    if (e + 4 <= end) {
        int myi = csr[e + q];
        int r0 = __shfl_sync(qmask, myi, qbase + 0);
        int r1 = __shfl_sync(qmask, myi, qbase + 1);
        int r2 = __shfl_sync(qmask, myi, qbase + 2);
        int r3 = __shfl_sync(qmask, myi, qbase + 3);
        uint2 u0 = src[r0 * 4 + q];
        uint2 u1 = src[r1 * 4 + q];
        uint2 u2 = src[r2 * 4 + q];
        uint2 u3 = src[r3 * 4 + q];
        uint2 p01 = h4add(u0, u1);
        uint2 p23 = h4add(u2, u3);
        f4acc(acc, h4_to_f4(p01)); f4acc(acc, h4_to_f4(p23));
        e += 4;
    }
    int rem = end - e;
    if (rem > 0) {
        int myi = (q < rem) ? csr[e + q] : 0;
        for (int j = 0; j < rem; j++) {
            int r = __shfl_sync(qmask, myi, qbase + j);
            f4acc(acc, h4_to_f4(src[r * 4 + q]));
        }
    }
    return acc;
}

// ---------------- K4: layer1 gather + relu -----------------------------------
__global__ void __launch_bounds__(256) k_gather1(const float* __restrict__ b1) {
    int t = blockIdx.x * blockDim.x + threadIdx.x;
    int node = t >> 2;
    if (node >= N_NODES) return;
    int q = t & 3;
    int qbase = (threadIdx.x & 31) & ~3;
    unsigned qmask = 0xFu << qbase;
    int cnt = g_cnt[node];
    float d = rsqrtf((float)(cnt + 1));
    if (cnt > BUCKET) cnt = BUCKET;
    int beg = node * BUCKET;
    int end = beg + cnt;
    float4 acc = gather_acc(g_hs1h, beg, end, q, qmask, qbase);
    float4 self = h4_to_f4(g_hs1h[node * 4 + q]);
    float4 bb = ((const float4*)b1)[q];
    float4 h;
    h.x = fmaxf(fmaf(acc.x + self.x, d, bb.x), 0.f) * d;
    h.y = fmaxf(fmaf(acc.y + self.y, d, bb.y), 0.f) * d;
    h.z = fmaxf(fmaf(acc.z + self.z, d, bb.z), 0.f) * d;
    h.w = fmaxf(fmaf(acc.w + self.w, d, bb.w), 0.f) * d;
    g_hs2h[node * 4 + q] = f4_to_h4(h);
}

// ---------------- K5: layer2 gather fused @W2 + b2 -> out; cleans g_cnt ------
// Epilogue remap: thread q computes the 10 CONTIGUOUS outputs [10q, 10q+10).
// All W2/bias/output accesses are 8B vectors; warp stores cover 8x160B
// contiguous runs (sector-perfect) instead of 10 stride-4 scalar stores.
__global__ void __launch_bounds__(256) k_gather2(const float* __restrict__ W2,
                                                 const float* __restrict__ b2,
                                                 float* __restrict__ out) {
    __shared__ float w2s[HIDDEN * N_CLASSES];
    __shared__ float b2s[N_CLASSES];
    {
        int tt = threadIdx.x;
        for (int i = tt; i < HIDDEN * N_CLASSES; i += 256) w2s[i] = W2[i];
        if (tt < N_CLASSES) b2s[tt] = b2[tt];
        __syncthreads();
    }
    int t = blockIdx.x * blockDim.x + threadIdx.x;
    int node = t >> 2;
    bool valid = (node < N_NODES);
    int node_c = valid ? node : 0;
    int q = t & 3;
    int lane = threadIdx.x & 31;
    int qbase = lane & ~3;
    unsigned qmask = 0xFu << qbase;

    int cnt = valid ? g_cnt[node_c] : 0;     // invalid quads don't touch g_cnt
    float d = rsqrtf((float)(cnt + 1));
    if (valid && q == 0) g_cnt[node_c] = 0;  // self-clean for next replay
    if (cnt > BUCKET) cnt = BUCKET;
    int beg = node_c * BUCKET;
    int end = beg + cnt;
    float4 acc = gather_acc(g_hs2h, beg, end, q, qmask, qbase);
    float4 self = h4_to_f4(g_hs2h[node_c * 4 + q]);
    float av[4];
    av[0] = (acc.x + self.x) * d;
    av[1] = (acc.y + self.y) * d;
    av[2] = (acc.z + self.z) * d;
    av[3] = (acc.w + self.w) * d;

    // packed f32x2 accumulators for outputs (10q+2m, 10q+2m+1), m=0..4
    unsigned long long o2[5];
    const int ob = 10 * q;
#pragma unroll
    for (int m = 0; m < 5; m++)
        o2[m] = *reinterpret_cast<const unsigned long long*>(&b2s[ob + 2 * m]);

#pragma unroll
    for (int k = 0; k < HIDDEN; k++) {
        float v = __shfl_sync(0xffffffffu, av[k & 3], qbase + (k >> 2));
        unsigned long long v2 = pack2(v, v);
        const float* wrow = &w2s[k * N_CLASSES + ob];
#pragma unroll
        for (int m = 0; m < 5; m++)
            ffma2(o2[m], v2, *reinterpret_cast<const unsigned long long*>(&wrow[2 * m]));
    }
    if (valid) {
        float* op = out + (size_t)node * N_CLASSES + ob;
#pragma unroll
        for (int m = 0; m < 5; m++)
            *reinterpret_cast<float2*>(&op[2 * m]) = unpack2(o2[m]);
    }
}

// ---------------- launch: 5 kernels; fillb overlaps gemm1 --------------------
extern "C" void kernel_launch(void* const* d_in, const int* in_sizes, int n_in,
                              void* d_out, int out_size) {
    const float* x  = (const float*)d_in[0];
    const void*  ei = d_in[1];
    const float* W1 = (const float*)d_in[2];
    const float* b1 = (const float*)d_in[3];
    const float* W2 = (const float*)d_in[4];
    const float* b2 = (const float*)d_in[5];
    float* out = (float*)d_out;

    // fork: GEMM1 on a side stream (independent of edge processing)
    cudaStream_t s2;
    cudaStreamCreateWithFlags(&s2, cudaStreamNonBlocking);
    cudaEvent_t evA, evB;
    cudaEventCreateWithFlags(&evA, cudaEventDisableTiming);
    cudaEventCreateWithFlags(&evB, cudaEventDisableTiming);
    cudaEventRecord(evA, 0);
    cudaStreamWaitEvent(s2, evA, 0);
    k_gemm1<<<(N_NODES + 127) / 128, 128, 0, s2>>>(x, W1);
    cudaEventRecord(evB, s2);

    // main stream: single-pass bucket CSR build (overlaps gemm1)
    k_fillb<<<(N_EDGES / 4 + 255) / 256, 256>>>(ei);

    // join, then scale + gathers
    cudaStreamWaitEvent(0, evB, 0);
    k_scale<<<(N_NODES * 4 + 255) / 256, 256>>>();
    k_gather1<<<(N_NODES * 4 + 255) / 256, 256>>>(b1);
    k_gather2<<<(N_NODES * 4 + 255) / 256, 256>>>(W2, b2, out);

    cudaEventDestroy(evA);
    cudaEventDestroy(evB);
    cudaStreamDestroy(s2);
}

// round 15
// speedup vs baseline: 1.3452x; 1.0467x over previous
#include <cuda_runtime.h>
#include <cuda_fp16.h>

#define N_NODES 100000
#define N_EDGES 1600000
#define F_IN 512
#define HIDDEN 16
#define N_CLASSES 40
#define BUCKET 128                     // CSR slots per node (P(deg>128) ~ 1e-60)

// ---------------- scratch (no device allocs; zero at module load) ------------
__device__ int   g_csr [N_NODES * BUCKET];   // bucket CSR: sources of in-edges
__device__ int   g_cnt [N_NODES];            // in-degree/cursor (self-cleaned by k_gather2)
__device__ uint2 g_hs1u[N_NODES * 4];        // x@W1 as fp16 (unscaled, gemm1 out)
__device__ uint2 g_hs1h[N_NODES * 4];        // (x@W1)*dis as fp16
__device__ uint2 g_hs2h[N_NODES * 4];        // relu(...)*dis as fp16

// ---------------- helpers ----------------
__device__ __forceinline__ unsigned long long pack2(float x, float y) {
    unsigned long long r;
    asm("mov.b64 %0, {%1,%2};" : "=l"(r) : "f"(x), "f"(y));
    return r;
}
__device__ __forceinline__ float2 unpack2(unsigned long long v) {
    float2 f;
    asm("mov.b64 {%0,%1}, %2;" : "=f"(f.x), "=f"(f.y) : "l"(v));
    return f;
}
__device__ __forceinline__ void ffma2(unsigned long long& d,
                                      unsigned long long a,
                                      unsigned long long b) {
    asm("fma.rn.f32x2 %0, %1, %2, %0;" : "+l"(d) : "l"(a), "l"(b));
}
__device__ __forceinline__ unsigned smem_u32(const void* p) {
    return (unsigned)__cvta_generic_to_shared(p);
}
__device__ __forceinline__ float4 h4_to_f4(uint2 u) {
    __half2 a = *reinterpret_cast<__half2*>(&u.x);
    __half2 b = *reinterpret_cast<__half2*>(&u.y);
    float2 fa = __half22float2(a), fb = __half22float2(b);
    return make_float4(fa.x, fa.y, fb.x, fb.y);
}
__device__ __forceinline__ uint2 f4_to_h4(float4 v) {
    __half2 a = __floats2half2_rn(v.x, v.y);
    __half2 b = __floats2half2_rn(v.z, v.w);
    uint2 u;
    u.x = *reinterpret_cast<unsigned*>(&a);
    u.y = *reinterpret_cast<unsigned*>(&b);
    return u;
}
// fp16 pairwise add of two packed-4-half values
__device__ __forceinline__ uint2 h4add(uint2 a, uint2 b) {
    __half2 ax = *reinterpret_cast<__half2*>(&a.x);
    __half2 ay = *reinterpret_cast<__half2*>(&a.y);
    __half2 bx = *reinterpret_cast<__half2*>(&b.x);
    __half2 by = *reinterpret_cast<__half2*>(&b.y);
    __half2 cx = __hadd2(ax, bx);
    __half2 cy = __hadd2(ay, by);
    uint2 c;
    c.x = *reinterpret_cast<unsigned*>(&cx);
    c.y = *reinterpret_cast<unsigned*>(&cy);
    return c;
}
__device__ __forceinline__ void f4acc(float4& a, float4 b) {
    a.x += b.x; a.y += b.y; a.z += b.z; a.w += b.w;
}

// Per-warp dtype detect: int64 (<2^31) => hi 32-bit words all zero.
__device__ __forceinline__ bool detect_is64(const void* ei, int tquad) {
    ulonglong2 raw = ((const ulonglong2*)ei)[tquad * 2];
    unsigned hi = (unsigned)(raw.x >> 32) | (unsigned)(raw.y >> 32);
    return __all_sync(0xffffffffu, hi == 0u);
}

// ---------------- K1: bucket-CSR fill (4 edges/thread), one pass --------------
__global__ void __launch_bounds__(256) k_fillb(const void* __restrict__ ei) {
    int t = blockIdx.x * blockDim.x + threadIdx.x;
    if (t * 4 >= N_EDGES) return;
    bool is64 = detect_is64(ei, t);
    int r0, r1, r2, r3, c0, c1, c2, c3;
    if (is64) {
        const longlong4* pr = (const longlong4*)ei;
        const longlong4* pc = (const longlong4*)((const char*)ei + (size_t)N_EDGES * 8);
        longlong4 vr = pr[t], vc = pc[t];
        r0 = (int)vr.x; r1 = (int)vr.y; r2 = (int)vr.z; r3 = (int)vr.w;
        c0 = (int)vc.x; c1 = (int)vc.y; c2 = (int)vc.z; c3 = (int)vc.w;
    } else {
        const int4* pr = (const int4*)ei;
        const int4* pc = (const int4*)((const char*)ei + (size_t)N_EDGES * 4);
        int4 vr = pr[t], vc = pc[t];
        r0 = vr.x; r1 = vr.y; r2 = vr.z; r3 = vr.w;
        c0 = vc.x; c1 = vc.y; c2 = vc.z; c3 = vc.w;
    }
    int p0 = atomicAdd(&g_cnt[c0], 1);
    int p1 = atomicAdd(&g_cnt[c1], 1);
    int p2 = atomicAdd(&g_cnt[c2], 1);
    int p3 = atomicAdd(&g_cnt[c3], 1);
    if (p0 < BUCKET) g_csr[c0 * BUCKET + p0] = r0;
    if (p1 < BUCKET) g_csr[c1 * BUCKET + p1] = r1;
    if (p2 < BUCKET) g_csr[c2 * BUCKET + p2] = r2;
    if (p3 < BUCKET) g_csr[c3 * BUCKET + p3] = r3;
}

// ---------------- K2 (side stream): GEMM1, cp.async double-buffered ----------
__device__ __forceinline__ void gemm1_stage(const float* __restrict__ x,
                                            const float* __restrict__ W1,
                                            unsigned xs_base, unsigned ws_base,
                                            int buf, int k0, int t, int n0) {
#pragma unroll
    for (int i = 0; i < 8; i++) {
        int f = i * 128 + t;
        int row = f >> 3, c4 = f & 7;
        int node = n0 + row;
        const float* src = x + (size_t)node * F_IN + k0 + c4 * 4;
        unsigned dst = xs_base + (unsigned)(buf * 1024 + row * 8 + (c4 ^ (row & 7))) * 16u;
        int sb = (node < N_NODES) ? 16 : 0;
        asm volatile("cp.async.cg.shared.global [%0], [%1], 16, %2;"
                     :: "r"(dst), "l"(src), "r"(sb) : "memory");
    }
    {
        const float* srcw = W1 + (size_t)(k0 + (t >> 2)) * HIDDEN + (t & 3) * 4;
        unsigned dstw = ws_base + (unsigned)(buf * 128 + t) * 16u;
        asm volatile("cp.async.cg.shared.global [%0], [%1], 16;"
                     :: "r"(dstw), "l"(srcw) : "memory");
    }
    asm volatile("cp.async.commit_group;" ::: "memory");
}

__global__ void __launch_bounds__(128) k_gemm1(const float* __restrict__ x,
                                               const float* __restrict__ W1) {
    __shared__ __align__(16) float4 xs[2][1024];   // 32 KB
    __shared__ __align__(16) float4 ws[2][128];    // 4 KB
    const int t = threadIdx.x;
    const int n0 = blockIdx.x * 128;
    const unsigned xs_base = smem_u32(&xs[0][0]);
    const unsigned ws_base = smem_u32(&ws[0][0]);

    unsigned long long acc[8];
#pragma unroll
    for (int p = 0; p < 8; p++) acc[p] = 0ull;

    gemm1_stage(x, W1, xs_base, ws_base, 0, 0, t, n0);

    const int tsw = t & 7;
#pragma unroll 1
    for (int tile = 0; tile < 16; tile++) {
        int buf = tile & 1;
        if (tile < 15) {
            gemm1_stage(x, W1, xs_base, ws_base, buf ^ 1, (tile + 1) * 32, t, n0);
            asm volatile("cp.async.wait_group 1;" ::: "memory");
        } else {
            asm volatile("cp.async.wait_group 0;" ::: "memory");
        }
        __syncthreads();

#pragma unroll
        for (int kk4 = 0; kk4 < 8; kk4++) {
            float4 xv = xs[buf][t * 8 + (kk4 ^ tsw)];
#pragma unroll
            for (int j = 0; j < 4; j++) {
                float xj = (j == 0) ? xv.x : (j == 1) ? xv.y : (j == 2) ? xv.z : xv.w;
                unsigned long long x2 = pack2(xj, xj);
                const ulonglong2* wp =
                    (const ulonglong2*)&ws[buf][(kk4 * 4 + j) * 4];
                ulonglong2 w0 = wp[0], w1 = wp[1], w2 = wp[2], w3 = wp[3];
                ffma2(acc[0], x2, w0.x); ffma2(acc[1], x2, w0.y);
                ffma2(acc[2], x2, w1.x); ffma2(acc[3], x2, w1.y);
                ffma2(acc[4], x2, w2.x); ffma2(acc[5], x2, w2.y);
                ffma2(acc[6], x2, w3.x); ffma2(acc[7], x2, w3.y);
            }
        }
        __syncthreads();
    }

    int node = n0 + t;
    if (node < N_NODES) {
#pragma unroll
        for (int p = 0; p < 4; p++) {
            float2 lo = unpack2(acc[2 * p]);
            float2 hi = unpack2(acc[2 * p + 1]);
            g_hs1u[node * 4 + p] = f4_to_h4(make_float4(lo.x, lo.y, hi.x, hi.y));
        }
    }
}

// ---------------- K3: hs1h = fp16(hs1u * rsqrt(deg+1)) -----------------------
__global__ void k_scale() {
    int t = blockIdx.x * blockDim.x + threadIdx.x;
    if (t >= N_NODES * 4) return;
    float d = rsqrtf((float)(g_cnt[t >> 2] + 1));
    float4 v = h4_to_f4(g_hs1u[t]);
    g_hs1h[t] = f4_to_h4(make_float4(v.x * d, v.y * d, v.z * d, v.w * d));
}

// ---------------- gather core: quad-per-node, fp16 + hadd2 pairing -----------
__device__ __forceinline__ float4 gather_acc(const uint2* __restrict__ src,
                                             int beg, int end, int q,
                                             unsigned qmask, int qbase) {
    const int* __restrict__ csr = g_csr;
    float4 acc = make_float4(0.f, 0.f, 0.f, 0.f);
    int e = beg;
    if (e + 8 <= end) {
        int ia = csr[e + 2 * q];
        int ib = csr[e + 2 * q + 1];
        for (; e + 8 <= end; ) {
            int e2 = e + 8;
            int na = 0, nb = 0;
            if (e2 + 8 <= end) {                 // prefetch next iter's indices
                na = csr[e2 + 2 * q];
                nb = csr[e2 + 2 * q + 1];
            }
            int r0 = __shfl_sync(qmask, ia, qbase + 0);
            int r1 = __shfl_sync(qmask, ib, qbase + 0);
            int r2 = __shfl_sync(qmask, ia, qbase + 1);
            int r3 = __shfl_sync(qmask, ib, qbase + 1);
            int r4 = __shfl_sync(qmask, ia, qbase + 2);
            int r5 = __shfl_sync(qmask, ib, qbase + 2);
            int r6 = __shfl_sync(qmask, ia, qbase + 3);
            int r7 = __shfl_sync(qmask, ib, qbase + 3);
            uint2 u0 = src[r0 * 4 + q];
            uint2 u1 = src[r1 * 4 + q];
            uint2 u2 = src[r2 * 4 + q];
            uint2 u3 = src[r3 * 4 + q];
            uint2 u4 = src[r4 * 4 + q];
            uint2 u5 = src[r5 * 4 + q];
            uint2 u6 = src[r6 * 4 + q];
            uint2 u7 = src[r7 * 4 + q];
            uint2 p01 = h4add(u0, u1);
            uint2 p23 = h4add(u2, u3);
            uint2 p45 = h4add(u4, u5);
            uint2 p67 = h4add(u6, u7);
            f4acc(acc, h4_to_f4(p01)); f4acc(acc, h4_to_f4(p23));
            f4acc(acc, h4_to_f4(p45)); f4acc(acc, h4_to_f4(p67));
            ia = na; ib = nb; e = e2;
        }
    }
    if (e + 4 <= end) {
        int myi = csr[e + q];
        int r0 = __shfl_sync(qmask, myi, qbase + 0);
        int r1 = __shfl_sync(qmask, myi, qbase + 1);
        int r2 = __shfl_sync(qmask, myi, qbase + 2);
        int r3 = __shfl_sync(qmask, myi, qbase + 3);
        uint2 u0 = src[r0 * 4 + q];
        uint2 u1 = src[r1 * 4 + q];
        uint2 u2 = src[r2 * 4 + q];
        uint2 u3 = src[r3 * 4 + q];
        uint2 p01 = h4add(u0, u1);
        uint2 p23 = h4add(u2, u3);
        f4acc(acc, h4_to_f4(p01)); f4acc(acc, h4_to_f4(p23));
        e += 4;
    }
    int rem = end - e;
    if (rem > 0) {
        int myi = (q < rem) ? csr[e + q] : 0;
        for (int j = 0; j < rem; j++) {
            int r = __shfl_sync(qmask, myi, qbase + j);
            f4acc(acc, h4_to_f4(src[r * 4 + q]));
        }
    }
    return acc;
}

// ---------------- K4: layer1 gather + relu (PDL: launches under k_scale) -----
__global__ void __launch_bounds__(256) k_gather1(const float* __restrict__ b1) {
    int t = blockIdx.x * blockDim.x + threadIdx.x;
    int node = t >> 2;
    int q = t & 3;
    int qbase = (threadIdx.x & 31) & ~3;
    unsigned qmask = 0xFu << qbase;

    // pre-sync work: only touches g_cnt/g_csr (written by k_fillb, 2 edges
    // upstream, transitively complete). g_hs1h is written by k_scale -> sync.
    int cnt = (node < N_NODES) ? g_cnt[node] : 0;
    float d = rsqrtf((float)(cnt + 1));
    if (cnt > BUCKET) cnt = BUCKET;
    int beg = node * BUCKET;
    int end = beg + cnt;

    cudaGridDependencySynchronize();          // wait for k_scale's g_hs1h
    if (node >= N_NODES) return;

    float4 acc = gather_acc(g_hs1h, beg, end, q, qmask, qbase);
    float4 self = h4_to_f4(g_hs1h[node * 4 + q]);
    float4 bb = ((const float4*)b1)[q];
    float4 h;
    h.x = fmaxf(fmaf(acc.x + self.x, d, bb.x), 0.f) * d;
    h.y = fmaxf(fmaf(acc.y + self.y, d, bb.y), 0.f) * d;
    h.z = fmaxf(fmaf(acc.z + self.z, d, bb.z), 0.f) * d;
    h.w = fmaxf(fmaf(acc.w + self.w, d, bb.w), 0.f) * d;
    g_hs2h[node * 4 + q] = f4_to_h4(h);
}

// ---------------- K5: layer2 gather fused @W2+b2 (PDL under k_gather1) -------
// Contiguous-output epilogue: thread q computes outputs [10q, 10q+10) as
// 5 packed f32x2 accumulators; warp stores 8x160B contiguous runs.
__global__ void __launch_bounds__(256) k_gather2(const float* __restrict__ W2,
                                                 const float* __restrict__ b2,
                                                 float* __restrict__ out) {
    __shared__ float w2s[HIDDEN * N_CLASSES];
    __shared__ float b2s[N_CLASSES];
    {
        // pre-sync prologue: stage weights (inputs, independent of k_gather1)
        int tt = threadIdx.x;
        for (int i = tt; i < HIDDEN * N_CLASSES; i += 256) w2s[i] = W2[i];
        if (tt < N_CLASSES) b2s[tt] = b2[tt];
        __syncthreads();
    }
    int t = blockIdx.x * blockDim.x + threadIdx.x;
    int node = t >> 2;
    bool valid = (node < N_NODES);
    int node_c = valid ? node : 0;
    int q = t & 3;
    int lane = threadIdx.x & 31;
    int qbase = lane & ~3;
    unsigned qmask = 0xFu << qbase;

    // g_cnt read + self-clean must happen AFTER the dependency sync:
    // k_gather1's pre-sync phase also reads g_cnt and may still be running.
    cudaGridDependencySynchronize();          // wait for k_gather1's g_hs2h

    int cnt = valid ? g_cnt[node_c] : 0;
    float d = rsqrtf((float)(cnt + 1));
    if (valid && q == 0) g_cnt[node_c] = 0;   // self-clean for next replay
    if (cnt > BUCKET) cnt = BUCKET;
    int beg = node_c * BUCKET;
    int end = beg + cnt;
    float4 acc = gather_acc(g_hs2h, beg, end, q, qmask, qbase);
    float4 self = h4_to_f4(g_hs2h[node_c * 4 + q]);
    float av[4];
    av[0] = (acc.x + self.x) * d;
    av[1] = (acc.y + self.y) * d;
    av[2] = (acc.z + self.z) * d;
    av[3] = (acc.w + self.w) * d;

    unsigned long long o2[5];
    const int ob = 10 * q;
#pragma unroll
    for (int m = 0; m < 5; m++)
        o2[m] = *reinterpret_cast<const unsigned long long*>(&b2s[ob + 2 * m]);

#pragma unroll
    for (int k = 0; k < HIDDEN; k++) {
        float v = __shfl_sync(0xffffffffu, av[k & 3], qbase + (k >> 2));
        unsigned long long v2 = pack2(v, v);
        const float* wrow = &w2s[k * N_CLASSES + ob];
#pragma unroll
        for (int m = 0; m < 5; m++)
            ffma2(o2[m], v2, *reinterpret_cast<const unsigned long long*>(&wrow[2 * m]));
    }
    if (valid) {
        float* op = out + (size_t)node * N_CLASSES + ob;
#pragma unroll
        for (int m = 0; m < 5; m++)
            *reinterpret_cast<float2*>(&op[2 * m]) = unpack2(o2[m]);
    }
}

// ---------------- launch: fork + PDL chain -----------------------------------
extern "C" void kernel_launch(void* const* d_in, const int* in_sizes, int n_in,
                              void* d_out, int out_size) {
    const float* x  = (const float*)d_in[0];
    const void*  ei = d_in[1];
    const float* W1 = (const float*)d_in[2];
    const float* b1 = (const float*)d_in[3];
    const float* W2 = (const float*)d_in[4];
    const float* b2 = (const float*)d_in[5];
    float* out = (float*)d_out;

    // fork: GEMM1 on a side stream (independent of edge processing)
    cudaStream_t s2;
    cudaStreamCreateWithFlags(&s2, cudaStreamNonBlocking);
    cudaEvent_t evA, evB;
    cudaEventCreateWithFlags(&evA, cudaEventDisableTiming);
    cudaEventCreateWithFlags(&evB, cudaEventDisableTiming);
    cudaEventRecord(evA, 0);
    cudaStreamWaitEvent(s2, evA, 0);
    k_gemm1<<<(N_NODES + 127) / 128, 128, 0, s2>>>(x, W1);
    cudaEventRecord(evB, s2);

    // main stream: single-pass bucket CSR build (overlaps gemm1)
    k_fillb<<<(N_EDGES / 4 + 255) / 256, 256>>>(ei);

    // join, then scale + gathers (gathers chained via PDL)
    cudaStreamWaitEvent(0, evB, 0);
    k_scale<<<(N_NODES * 4 + 255) / 256, 256>>>();

    cudaLaunchAttribute pdl;
    pdl.id = cudaLaunchAttributeProgrammaticStreamSerialization;
    pdl.val.programmaticStreamSerializationAllowed = 1;

    {
        cudaLaunchConfig_t cfg{};
        cfg.gridDim = dim3((N_NODES * 4 + 255) / 256);
        cfg.blockDim = dim3(256);
        cfg.dynamicSmemBytes = 0;
        cfg.stream = 0;
        cfg.attrs = &pdl;
        cfg.numAttrs = 1;
        cudaLaunchKernelEx(&cfg, k_gather1, b1);
    }
    {
        cudaLaunchConfig_t cfg{};
        cfg.gridDim = dim3((N_NODES * 4 + 255) / 256);
        cfg.blockDim = dim3(256);
        cfg.dynamicSmemBytes = 0;
        cfg.stream = 0;
        cfg.attrs = &pdl;
        cfg.numAttrs = 1;
        cudaLaunchKernelEx(&cfg, k_gather2, W2, b2, out);
    }

    cudaEventDestroy(evA);
    cudaEventDestroy(evB);
    cudaStreamDestroy(s2);
}